// round 2
// baseline (speedup 1.0000x reference)
#include <cuda_runtime.h>
#include <cstdint>

#define IN_DIM 1024     // 2*L1
#define LXD    32
#define NBUCK  8
#define MAXB   65536
#define BK     32
#define MTILE  256
#define NTHR   128
#define NSTEP  (IN_DIM / BK)   // 32

// ---------------- device scratch (no allocation allowed) ----------------
__device__ float g_WcT[NBUCK * IN_DIM * LXD];   // [bucket][k][j] : w0 + w_fact, transposed
__device__ int   g_cnt[NBUCK];
__device__ int   g_list[NBUCK * MAXB];

// ---------------- small PTX helpers ----------------
__device__ __forceinline__ unsigned sptr(const void* p) {
    return (unsigned)__cvta_generic_to_shared(p);
}
__device__ __forceinline__ void cp8(void* dst, const void* src) {
    asm volatile("cp.async.ca.shared.global [%0], [%1], 8;\n" :: "r"(sptr(dst)), "l"(src));
}
__device__ __forceinline__ void cp16(void* dst, const void* src) {
    asm volatile("cp.async.cg.shared.global [%0], [%1], 16;\n" :: "r"(sptr(dst)), "l"(src));
}
__device__ __forceinline__ void cp_commit() { asm volatile("cp.async.commit_group;\n"); }
template<int N> __device__ __forceinline__ void cp_wait() {
    asm volatile("cp.async.wait_group %0;\n" :: "n"(N));
}
__device__ __forceinline__ unsigned long long pack2(float x) {
    unsigned long long r;
    asm("mov.b64 %0, {%1, %2};" : "=l"(r) : "f"(x), "f"(x));
    return r;
}
__device__ __forceinline__ void fma2(unsigned long long& d,
                                     unsigned long long a, unsigned long long b) {
    asm("fma.rn.f32x2 %0, %1, %2, %0;" : "+l"(d) : "l"(a), "l"(b));
}
__device__ __forceinline__ float2 unpack2(unsigned long long a) {
    float2 v;
    asm("mov.b64 {%0, %1}, %2;" : "=f"(v.x), "=f"(v.y) : "l"(a));
    return v;
}

// ---------------- kernel 1: zero counters + build combined transposed weights ----------------
__global__ void prep_kernel(const float* __restrict__ w0, const float* __restrict__ w_fact) {
    int idx = blockIdx.x * blockDim.x + threadIdx.x;   // NBUCK*IN_DIM*LXD = 262144
    if (idx < NBUCK * IN_DIM * LXD) {
        int j = idx & (LXD - 1);
        int k = (idx >> 5) & (IN_DIM - 1);
        int b = idx >> 15;
        g_WcT[idx] = w0[(b * LXD + j) * IN_DIM + k] + w_fact[j * IN_DIM + k];
    }
    if (blockIdx.x == 0 && threadIdx.x < NBUCK) g_cnt[threadIdx.x] = 0;
}

// ---------------- kernel 2: bin rows by bucket (warp-aggregated atomics) ----------------
// NOTE: ls_indices is int32 on the wire (JAX without x64 aliases jnp.int64 -> int32).
__global__ void bin_kernel(const int* __restrict__ ls, int B) {
    int i = blockIdx.x * blockDim.x + threadIdx.x;
    if (i >= B) return;
    int b = ls[i] & (NBUCK - 1);
    unsigned active = __activemask();
    unsigned m = __match_any_sync(active, b);
    int lane = threadIdx.x & 31;
    int leader = __ffs(m) - 1;
    int rank = __popc(m & ((1u << lane) - 1u));
    int base = 0;
    if (lane == leader) base = atomicAdd(&g_cnt[b], __popc(m));
    base = __shfl_sync(m, base, leader);
    g_list[b * MAXB + base + rank] = i;
}

// ---------------- kernel 3: binned gathered GEMM + fused MLP ----------------
struct Smem {
    float Xs[2][MTILE][BK + 2];       // stride 34 floats (8B-aligned rows, low-conflict)
    float Ws[2][BK][LXD];             // [kk][j], 16B-aligned rows
    const float* xptr[MTILE];
    int   perm[MTILE];
    float w1T[LXD * LXD];             // w1 transposed: [i][j]
    float b0s[LXD], b1s[LXD], w2s[LXD];
    float b2s;
};

__device__ __forceinline__ void process_row(const Smem* S, const unsigned long long* acc,
                                            int row, float* __restrict__ out) {
    if (row < 0) return;
    float h[LXD];
#pragma unroll
    for (int q = 0; q < LXD / 2; ++q) {
        float2 v = unpack2(acc[q]);
        h[2 * q] = v.x; h[2 * q + 1] = v.y;
    }
    float h2[LXD];
#pragma unroll
    for (int j = 0; j < LXD; ++j) h2[j] = S->b1s[j];
#pragma unroll
    for (int i = 0; i < LXD; ++i) {
        float xi = h[i] + S->b0s[i];
        xi = fminf(fmaxf(xi, 0.0f), 1.0f);
        const float* wr = &S->w1T[i * LXD];
#pragma unroll
        for (int j = 0; j < LXD; ++j) h2[j] = fmaf(xi, wr[j], h2[j]);
    }
    float o = S->b2s;
#pragma unroll
    for (int j = 0; j < LXD; ++j) {
        float c = fminf(fmaxf(h2[j], 0.0f), 1.0f);
        o = fmaf(c, S->w2s[j], o);
    }
    out[row] = o;
}

__global__ void __launch_bounds__(NTHR, 2)
main_kernel(const float* __restrict__ x,
            const float* __restrict__ b0, const float* __restrict__ b1,
            const float* __restrict__ w1, const float* __restrict__ w2,
            const float* __restrict__ b2,
            float* __restrict__ out, int B) {
    extern __shared__ char smem_raw[];
    Smem* S = reinterpret_cast<Smem*>(smem_raw);

    const int tile = blockIdx.x;
    const int b    = blockIdx.y;
    const int cnt  = g_cnt[b];
    const int start = tile * MTILE;
    if (start >= cnt) return;

    const int t = threadIdx.x;

    // ---- stage per-CTA metadata + small weights ----
    for (int m = t; m < MTILE; m += NTHR) {
        int g = start + m;
        int ridx = (g < cnt) ? g_list[b * MAXB + g] : -1;
        S->perm[m] = ridx;
        S->xptr[m] = x + (size_t)(ridx < 0 ? 0 : ridx) * IN_DIM;
    }
    for (int idx = t; idx < LXD * LXD; idx += NTHR) {
        int i = idx >> 5, j = idx & 31;
        S->w1T[idx] = w1[(b * LXD + j) * LXD + i];
    }
    if (t < LXD) {
        S->b0s[t] = b0[b * LXD + t];
        S->b1s[t] = b1[b * LXD + t];
        S->w2s[t] = w2[b * LXD + t];
    }
    if (t == 0) S->b2s = b2[b];
    __syncthreads();

    const float* wct = g_WcT + (size_t)b * IN_DIM * LXD;
    const int k2 = t & 15;       // 16 x 2-float chunks cover 32 k
    const int rb = t >> 4;       // 8 row-lanes

    // ---- async loader for one K-step ----
    auto load_step = [&](int stage, int k0) {
#pragma unroll
        for (int p = 0; p < MTILE / 8; ++p) {
            int r = p * 8 + rb;
            const float* gp = S->xptr[r] + k0 + k2 * 2;
            cp8(&S->Xs[stage][r][k2 * 2], gp);
        }
        const float* wsrc = wct + (size_t)k0 * LXD + t * 8;
        float* wdst = &S->Ws[stage][0][0] + t * 8;
        cp16(wdst, wsrc);
        cp16(wdst + 4, wsrc + 4);
        cp_commit();
    };

    unsigned long long acc0[LXD / 2], acc1[LXD / 2];
#pragma unroll
    for (int q = 0; q < LXD / 2; ++q) { acc0[q] = 0ull; acc1[q] = 0ull; }

    load_step(0, 0);

#pragma unroll 1
    for (int s = 0; s < NSTEP; ++s) {
        const int stage = s & 1;
        if (s + 1 < NSTEP) {
            load_step(stage ^ 1, (s + 1) * BK);
            cp_wait<1>();
        } else {
            cp_wait<0>();
        }
        __syncthreads();

#pragma unroll 8
        for (int kk = 0; kk < BK; ++kk) {
            float x0 = S->Xs[stage][t][kk];
            float x1 = S->Xs[stage][t + 128][kk];
            unsigned long long X0 = pack2(x0);
            unsigned long long X1 = pack2(x1);
            const ulonglong2* wp =
                reinterpret_cast<const ulonglong2*>(&S->Ws[stage][kk][0]);
#pragma unroll
            for (int q = 0; q < 8; ++q) {
                ulonglong2 w = wp[q];
                fma2(acc0[2 * q],     X0, w.x);
                fma2(acc0[2 * q + 1], X0, w.y);
                fma2(acc1[2 * q],     X1, w.x);
                fma2(acc1[2 * q + 1], X1, w.y);
            }
        }
        __syncthreads();
    }

    // ---- fused layer1 + layer2 epilogue ----
    process_row(S, acc0, S->perm[t], out);
    process_row(S, acc1, S->perm[t + 128], out);
}

// ---------------- launch ----------------
extern "C" void kernel_launch(void* const* d_in, const int* in_sizes, int n_in,
                              void* d_out, int out_size) {
    const float* x      = (const float*)d_in[0];
    const int*   ls     = (const int*)d_in[1];   // int32 on the wire (JAX x64 disabled)
    const float* w_fact = (const float*)d_in[2];
    const float* w0     = (const float*)d_in[3];
    const float* b0     = (const float*)d_in[4];
    const float* w1     = (const float*)d_in[5];
    const float* b1     = (const float*)d_in[6];
    const float* w2     = (const float*)d_in[7];
    const float* b2     = (const float*)d_in[8];
    float*       out    = (float*)d_out;

    const int B = in_sizes[0] / IN_DIM;

    // 1. zero counters + precompute combined transposed weights
    prep_kernel<<<(NBUCK * IN_DIM * LXD + 255) / 256, 256>>>(w0, w_fact);
    // 2. bin rows by bucket
    bin_kernel<<<(B + 255) / 256, 256>>>(ls, B);
    // 3. binned gathered GEMM + fused MLP
    static const size_t smem_bytes = sizeof(Smem);
    cudaFuncSetAttribute(main_kernel, cudaFuncAttributeMaxDynamicSharedMemorySize,
                         (int)smem_bytes);
    dim3 grid((B + MTILE - 1) / MTILE, NBUCK);
    main_kernel<<<grid, NTHR, smem_bytes>>>(x, b0, b1, w1, w2, b2, out, B);
}